// round 1
// baseline (speedup 1.0000x reference)
#include <cuda_runtime.h>
#include <cuda_bf16.h>
#include <math.h>

// Problem constants
#define B_  4
#define S_  2048
#define D_  1024
#define H_  16
#define HD_ 64
#define M_  (B_ * S_)        // 8192 rows

// Scratch (static device allocations are allowed; cudaMalloc is not)
__device__ float g_qkv[(size_t)M_ * 3 * D_];   // [8192][3072]
__device__ float g_attn[(size_t)M_ * D_];      // [8192][1024]

// ---------------------------------------------------------------------------
// SGEMM: C[M,N] = A[M,K] @ B[K,N], all row-major fp32.
// 128x128 block, BK=16, 256 threads, 8x8 per-thread tile.
// M,N multiples of 128; K multiple of 16 (true for all our shapes).
// ---------------------------------------------------------------------------
__global__ __launch_bounds__(256) void sgemm_kernel(
    const float* __restrict__ A, const float* __restrict__ Bm,
    float* __restrict__ C, int M, int N, int K)
{
    __shared__ float As[16 * 132];  // transposed: As[k][m], pad 132
    __shared__ float Bs[16 * 132];  // Bs[k][n], pad 132

    const int t  = threadIdx.x;
    const int ty = t >> 4;          // 0..15  -> rows
    const int tx = t & 15;          // 0..15  -> cols
    const int row0 = blockIdx.y * 128;
    const int col0 = blockIdx.x * 128;

    float acc[8][8];
#pragma unroll
    for (int i = 0; i < 8; i++)
#pragma unroll
        for (int j = 0; j < 8; j++) acc[i][j] = 0.0f;

    for (int k0 = 0; k0 < K; k0 += 16) {
        // Load A tile [128][16] -> As[k][m] (transposed)
#pragma unroll
        for (int r = 0; r < 2; r++) {
            int f   = t + r * 256;           // 0..511
            int ar  = f >> 2;                // 0..127
            int ac4 = (f & 3) * 4;           // 0,4,8,12
            float4 v = *(const float4*)(A + (size_t)(row0 + ar) * K + k0 + ac4);
            As[(ac4 + 0) * 132 + ar] = v.x;
            As[(ac4 + 1) * 132 + ar] = v.y;
            As[(ac4 + 2) * 132 + ar] = v.z;
            As[(ac4 + 3) * 132 + ar] = v.w;
        }
        // Load B tile [16][128] -> Bs[k][n]
#pragma unroll
        for (int r = 0; r < 2; r++) {
            int f  = t + r * 256;            // 0..511
            int br = f >> 5;                 // 0..15
            int bc = (f & 31) * 4;           // 0..124
            float4 v = *(const float4*)(Bm + (size_t)(k0 + br) * N + col0 + bc);
            *(float4*)&Bs[br * 132 + bc] = v;
        }
        __syncthreads();

#pragma unroll
        for (int kk = 0; kk < 16; kk++) {
            float4 a0 = *(float4*)&As[kk * 132 + ty * 8];
            float4 a1 = *(float4*)&As[kk * 132 + ty * 8 + 4];
            float4 b0 = *(float4*)&Bs[kk * 132 + tx * 8];
            float4 b1 = *(float4*)&Bs[kk * 132 + tx * 8 + 4];
            float av[8] = {a0.x,a0.y,a0.z,a0.w,a1.x,a1.y,a1.z,a1.w};
            float bv[8] = {b0.x,b0.y,b0.z,b0.w,b1.x,b1.y,b1.z,b1.w};
#pragma unroll
            for (int i = 0; i < 8; i++)
#pragma unroll
                for (int j = 0; j < 8; j++)
                    acc[i][j] = fmaf(av[i], bv[j], acc[i][j]);
        }
        __syncthreads();
    }

#pragma unroll
    for (int i = 0; i < 8; i++) {
        size_t crow = (size_t)(row0 + ty * 8 + i) * N + col0 + tx * 8;
        float4 o0 = {acc[i][0], acc[i][1], acc[i][2], acc[i][3]};
        float4 o1 = {acc[i][4], acc[i][5], acc[i][6], acc[i][7]};
        *(float4*)(C + crow)     = o0;
        *(float4*)(C + crow + 4) = o1;
    }
}

// ---------------------------------------------------------------------------
// Causal flash attention, fp32.
// qkv: [B*S][3072] where cols [0,1024)=Q, [1024,2048)=K, [2048,3072)=V
// out: [B*S][1024] attention output (s-major, head-concat layout)
// Block: 256 threads (16x16). BM=128 q rows, BN=64 keys per tile, HD=64.
// Thread (ty,tx): rows ty*8..+7, score-cols / hd-cols tx*4..+3.
// Dynamic smem: Qt[64][132] Kt[64][68] Vs[64][68] Ps[64][132] = 100 KB.
// ---------------------------------------------------------------------------
#define ATTN_SMEM_FLOATS (64*132 + 64*68 + 64*68 + 64*132)

__global__ __launch_bounds__(256) void attn_kernel(
    const float* __restrict__ qkv, float* __restrict__ out)
{
    extern __shared__ float sm[];
    float* Qt = sm;                      // [d][i]  64 x 132
    float* Kt = Qt + 64 * 132;           // [d][j]  64 x 68
    float* Vs = Kt + 64 * 68;            // [j][d]  64 x 68
    float* Ps = Vs + 64 * 68;            // [j][i]  64 x 132

    const int t  = threadIdx.x;
    const int ty = t >> 4;
    const int tx = t & 15;
    const int qt = blockIdx.x;           // 0..15
    const int h  = blockIdx.y;           // 0..15
    const int b  = blockIdx.z;           // 0..3
    const int q0 = qt * 128;
    const float scale = 0.125f;          // 1/sqrt(64)

    // Load Q tile (scaled), transposed to Qt[d][i]
    {
        const float* qb = qkv + (size_t)(b * S_ + q0) * 3072 + h * HD_;
#pragma unroll
        for (int r = 0; r < 8; r++) {
            int idx = r * 256 + t;
            int i   = idx >> 4;
            int d4  = (idx & 15) * 4;
            float4 v = *(const float4*)(qb + (size_t)i * 3072 + d4);
            Qt[(d4 + 0) * 132 + i] = v.x * scale;
            Qt[(d4 + 1) * 132 + i] = v.y * scale;
            Qt[(d4 + 2) * 132 + i] = v.z * scale;
            Qt[(d4 + 3) * 132 + i] = v.w * scale;
        }
    }

    float mrow[8], lrow[8], O[8][4];
#pragma unroll
    for (int i = 0; i < 8; i++) {
        mrow[i] = -INFINITY; lrow[i] = 0.0f;
#pragma unroll
        for (int j = 0; j < 4; j++) O[i][j] = 0.0f;
    }

    const int ktiles = 2 * qt + 2;       // only up to (and including) diagonal
    for (int kt = 0; kt < ktiles; kt++) {
        __syncthreads();                 // also covers Qt load on first iter
        const int k0 = kt * 64;
        // Load K (transposed -> Kt[d][j]) and V (-> Vs[j][d])
        {
            const float* kb = qkv + (size_t)(b * S_ + k0) * 3072 + 1024 + h * HD_;
            const float* vb = kb + 1024;
#pragma unroll
            for (int r = 0; r < 4; r++) {
                int idx = r * 256 + t;
                int j   = idx >> 4;
                int d4  = (idx & 15) * 4;
                float4 kv = *(const float4*)(kb + (size_t)j * 3072 + d4);
                Kt[(d4 + 0) * 68 + j] = kv.x;
                Kt[(d4 + 1) * 68 + j] = kv.y;
                Kt[(d4 + 2) * 68 + j] = kv.z;
                Kt[(d4 + 3) * 68 + j] = kv.w;
                float4 vv = *(const float4*)(vb + (size_t)j * 3072 + d4);
                *(float4*)&Vs[j * 68 + d4] = vv;
            }
        }
        __syncthreads();

        // S = (scaled Q) @ K^T   -> S[8][4] per thread
        float Sv[8][4];
#pragma unroll
        for (int i = 0; i < 8; i++)
#pragma unroll
            for (int j = 0; j < 4; j++) Sv[i][j] = 0.0f;

#pragma unroll 4
        for (int d = 0; d < 64; d++) {
            float4 qa = *(float4*)&Qt[d * 132 + ty * 8];
            float4 qb2 = *(float4*)&Qt[d * 132 + ty * 8 + 4];
            float4 kf = *(float4*)&Kt[d * 68 + tx * 4];
            float qv[8] = {qa.x,qa.y,qa.z,qa.w,qb2.x,qb2.y,qb2.z,qb2.w};
            float kv[4] = {kf.x,kf.y,kf.z,kf.w};
#pragma unroll
            for (int i = 0; i < 8; i++)
#pragma unroll
                for (int j = 0; j < 4; j++)
                    Sv[i][j] = fmaf(qv[i], kv[j], Sv[i][j]);
        }

        // Causal mask (only the two diagonal tiles ever need it)
        if (k0 + 63 > q0) {
#pragma unroll
            for (int i = 0; i < 8; i++) {
                int gi = q0 + ty * 8 + i;
#pragma unroll
                for (int j = 0; j < 4; j++) {
                    int gj = k0 + tx * 4 + j;
                    if (gj > gi) Sv[i][j] = -INFINITY;
                }
            }
        }

        // Online softmax update + write P to Ps[j][i]
#pragma unroll
        for (int i = 0; i < 8; i++) {
            float mx = fmaxf(fmaxf(Sv[i][0], Sv[i][1]), fmaxf(Sv[i][2], Sv[i][3]));
#pragma unroll
            for (int o = 8; o >= 1; o >>= 1)
                mx = fmaxf(mx, __shfl_xor_sync(0xffffffffu, mx, o, 16));
            float mn = fmaxf(mrow[i], mx);
            float corr = __expf(mrow[i] - mn);
            mrow[i] = mn;
            float p0 = __expf(Sv[i][0] - mn);
            float p1 = __expf(Sv[i][1] - mn);
            float p2 = __expf(Sv[i][2] - mn);
            float p3 = __expf(Sv[i][3] - mn);
            float rs = p0 + p1 + p2 + p3;
#pragma unroll
            for (int o = 8; o >= 1; o >>= 1)
                rs += __shfl_xor_sync(0xffffffffu, rs, o, 16);
            lrow[i] = lrow[i] * corr + rs;
#pragma unroll
            for (int j = 0; j < 4; j++) O[i][j] *= corr;
            int ii = ty * 8 + i;
            Ps[(tx * 4 + 0) * 132 + ii] = p0;
            Ps[(tx * 4 + 1) * 132 + ii] = p1;
            Ps[(tx * 4 + 2) * 132 + ii] = p2;
            Ps[(tx * 4 + 3) * 132 + ii] = p3;
        }
        __syncthreads();

        // O += P @ V
#pragma unroll 4
        for (int j = 0; j < 64; j++) {
            float4 pa = *(float4*)&Ps[j * 132 + ty * 8];
            float4 pb = *(float4*)&Ps[j * 132 + ty * 8 + 4];
            float4 vf = *(float4*)&Vs[j * 68 + tx * 4];
            float pv[8] = {pa.x,pa.y,pa.z,pa.w,pb.x,pb.y,pb.z,pb.w};
            float vv[4] = {vf.x,vf.y,vf.z,vf.w};
#pragma unroll
            for (int i = 0; i < 8; i++)
#pragma unroll
                for (int d = 0; d < 4; d++)
                    O[i][d] = fmaf(pv[i], vv[d], O[i][d]);
        }
    }

    // Epilogue: normalize and store to [b,s, h*64 + d] layout
#pragma unroll
    for (int i = 0; i < 8; i++) {
        float inv = 1.0f / lrow[i];
        float4 o = {O[i][0] * inv, O[i][1] * inv, O[i][2] * inv, O[i][3] * inv};
        size_t row = (size_t)(b * S_ + q0 + ty * 8 + i);
        *(float4*)(out + row * D_ + h * HD_ + tx * 4) = o;
    }
}

// ---------------------------------------------------------------------------
extern "C" void kernel_launch(void* const* d_in, const int* in_sizes, int n_in,
                              void* d_out, int out_size)
{
    // Identify inputs by element count (all distinct):
    //   x: 8388608, causal_mask: 4194304 (unused), W_qkv: 3145728, W_out: 1048576
    const float* x = nullptr; const float* wqkv = nullptr; const float* wout = nullptr;
    for (int i = 0; i < n_in; i++) {
        if (in_sizes[i] == 8388608)      x    = (const float*)d_in[i];
        else if (in_sizes[i] == 3145728) wqkv = (const float*)d_in[i];
        else if (in_sizes[i] == 1048576) wout = (const float*)d_in[i];
    }
    float* out = (float*)d_out;

    void* qkv_p = nullptr; void* attn_p = nullptr;
    cudaGetSymbolAddress(&qkv_p, g_qkv);
    cudaGetSymbolAddress(&attn_p, g_attn);
    float* qkv  = (float*)qkv_p;
    float* attn = (float*)attn_p;

    static_assert(ATTN_SMEM_FLOATS * sizeof(float) == 102400, "smem size");
    cudaFuncSetAttribute(attn_kernel, cudaFuncAttributeMaxDynamicSharedMemorySize,
                         ATTN_SMEM_FLOATS * (int)sizeof(float));

    // 1) qkv = x @ W_qkv          [8192,1024] x [1024,3072]
    sgemm_kernel<<<dim3(3072 / 128, 8192 / 128), 256>>>(x, wqkv, qkv, M_, 3 * D_, D_);
    // 2) attention
    attn_kernel<<<dim3(S_ / 128, H_, B_), 256, ATTN_SMEM_FLOATS * sizeof(float)>>>(qkv, attn);
    // 3) out = attn @ W_out       [8192,1024] x [1024,1024]
    sgemm_kernel<<<dim3(1024 / 128, 8192 / 128), 256>>>(attn, wout, out, M_, D_, D_);
}

// round 4
// speedup vs baseline: 1.4526x; 1.4526x over previous
#include <cuda_runtime.h>
#include <cuda_bf16.h>
#include <math.h>
#include <cstdint>

// Problem constants
#define B_  4
#define S_  2048
#define D_  1024
#define H_  16
#define HD_ 64
#define M_  (B_ * S_)        // 8192 rows

// Scratch (static device allocations are allowed; cudaMalloc is not)
__device__ float g_qkv[(size_t)M_ * 3 * D_];   // [8192][3072]
__device__ float g_attn[(size_t)M_ * D_];      // [8192][1024]
__device__ __nv_bfloat16 g_x_hi[(size_t)M_ * D_];
__device__ __nv_bfloat16 g_x_lo[(size_t)M_ * D_];
__device__ __nv_bfloat16 g_attn_hi[(size_t)M_ * D_];
__device__ __nv_bfloat16 g_attn_lo[(size_t)M_ * D_];
__device__ __nv_bfloat16 g_wqkvT_hi[(size_t)3 * D_ * D_];   // [3072][1024]
__device__ __nv_bfloat16 g_wqkvT_lo[(size_t)3 * D_ * D_];
__device__ __nv_bfloat16 g_woutT_hi[(size_t)D_ * D_];       // [1024][1024]
__device__ __nv_bfloat16 g_woutT_lo[(size_t)D_ * D_];

// ---------------------------------------------------------------------------
// PTX helpers: ldmatrix + mma.sync (baseline PTX, no 'a'-arch features)
// ---------------------------------------------------------------------------
__device__ __forceinline__ uint32_t smem_u32(const void* p) {
    uint32_t a;
    asm("{ .reg .u64 t; cvta.to.shared.u64 t, %1; cvt.u32.u64 %0, t; }" : "=r"(a) : "l"(p));
    return a;
}

#define LDSM_X4(r0, r1, r2, r3, addr) \
    asm volatile("ldmatrix.sync.aligned.m8n8.x4.shared.b16 {%0,%1,%2,%3}, [%4];" \
                 : "=r"(r0), "=r"(r1), "=r"(r2), "=r"(r3) : "r"(addr))

#define MMA16816(d, a, bb0, bb1) \
    asm volatile("mma.sync.aligned.m16n8k16.row.col.f32.bf16.bf16.f32 " \
                 "{%0,%1,%2,%3}, {%4,%5,%6,%7}, {%8,%9}, {%0,%1,%2,%3};" \
                 : "+f"((d)[0]), "+f"((d)[1]), "+f"((d)[2]), "+f"((d)[3]) \
                 : "r"((a)[0]), "r"((a)[1]), "r"((a)[2]), "r"((a)[3]), \
                   "r"(bb0), "r"(bb1))

// ---------------------------------------------------------------------------
// bf16 split-3 GEMM via mma.sync:  C[M,N](fp32) = Ahi*Bhi + Ahi*Blo + Alo*Bhi
// A: [M][K] bf16 row-major. B: [N][K] bf16 row-major (weights pre-transposed).
// Tile 128x128, BK=32, 256 threads (8 warps, 2x4; warp tile 64x32),
// double-buffered smem (pitch 40 bf16 = 80B, conflict-free ldmatrix).
// Requires M%128==0, N%128==0, K%32==0.
// ---------------------------------------------------------------------------
#define GPITCH 40                         // bf16 elems per smem row
#define GSTAGE (128 * GPITCH * 2)         // bytes per (A or B) stage = 10240
#define GEMM_SMEM_BYTES (4 * GSTAGE)      // 2 stages x (A+B) = 40960

__global__ __launch_bounds__(256, 2)
void gemm_mma_kernel(const __nv_bfloat16* __restrict__ Ahi, const __nv_bfloat16* __restrict__ Alo,
                     const __nv_bfloat16* __restrict__ Bhi, const __nv_bfloat16* __restrict__ Blo,
                     float* __restrict__ C, int Ndim, int Kdim)
{
    extern __shared__ __align__(16) char smem[];
    const uint32_t sb = smem_u32(smem);

    const int t   = threadIdx.x;
    const int l   = t & 31;
    const int wid = t >> 5;
    const int wm  = wid >> 2;             // 0..1  (64-row band)
    const int wn  = wid & 3;              // 0..3  (32-col band)
    const int row0 = blockIdx.y * 128, col0 = blockIdx.x * 128;

    const __nv_bfloat16* Ap[3] = {Ahi, Ahi, Alo};
    const __nv_bfloat16* Bp[3] = {Bhi, Blo, Bhi};
    const int KCH = Kdim >> 5;            // K-chunks of 32
    const int NC  = 3 * KCH;

    // per-thread ldg/sts mapping: 512 16B-chunks per matrix per stage,
    // q in {t, t+256}: row = q>>2 (0..127), cc = q&3 (16B chunk in row)
    const int r1 = t >> 2, cc = t & 3;
    const int r2 = 64 + r1;
    const uint32_t so1 = (uint32_t)(r1 * 80 + cc * 16);
    const uint32_t so2 = (uint32_t)(r2 * 80 + cc * 16);

    float acc[4][4][4];
#pragma unroll
    for (int i = 0; i < 4; i++)
#pragma unroll
        for (int j = 0; j < 4; j++)
#pragma unroll
            for (int k = 0; k < 4; k++) acc[i][j][k] = 0.0f;

    uint4 ra1, ra2, rb1, rb2;
    {   // prefetch chunk 0
        const __nv_bfloat16* Ag = Ap[0];
        const __nv_bfloat16* Bg = Bp[0];
        ra1 = *(const uint4*)(Ag + (size_t)(row0 + r1) * Kdim + cc * 8);
        ra2 = *(const uint4*)(Ag + (size_t)(row0 + r2) * Kdim + cc * 8);
        rb1 = *(const uint4*)(Bg + (size_t)(col0 + r1) * Kdim + cc * 8);
        rb2 = *(const uint4*)(Bg + (size_t)(col0 + r2) * Kdim + cc * 8);
    }
    {   // store stage 0
        uint32_t As = sb, Bs = sb + GSTAGE;
        *(uint4*)(smem + (As - sb) + so1) = ra1;
        *(uint4*)(smem + (As - sb) + so2) = ra2;
        *(uint4*)(smem + (Bs - sb) + so1) = rb1;
        *(uint4*)(smem + (Bs - sb) + so2) = rb2;
    }

    // ldmatrix base offsets for this thread (lane-dependent rows)
    // A tile x4 (mtile mt, kstep ks): row = wm*64 + mt*16 + (l&15), k = ks*16 + (l>>4)*8
    // B tile x4 (pair np, ks): n = wn*32 + np*16 + ((l>>4)&1)*8 + (l&7), k = ks*16 + ((l>>3)&1)*8
    const uint32_t a_lrow = (uint32_t)(wm * 64 + (l & 15));
    const uint32_t a_lk   = (uint32_t)((l >> 4) * 8);
    const uint32_t b_lrow = (uint32_t)(wn * 32 + ((l >> 4) & 1) * 8 + (l & 7));
    const uint32_t b_lk   = (uint32_t)(((l >> 3) & 1) * 8);

    for (int c = 0; c < NC; c++) {
        __syncthreads();
        const int s = c & 1;

        if (c + 1 < NC) {   // prefetch next chunk
            const int c1 = c + 1;
            const int pidx = c1 / KCH;
            const int k0 = (c1 - pidx * KCH) << 5;
            const __nv_bfloat16* Ag = Ap[pidx];
            const __nv_bfloat16* Bg = Bp[pidx];
            ra1 = *(const uint4*)(Ag + (size_t)(row0 + r1) * Kdim + k0 + cc * 8);
            ra2 = *(const uint4*)(Ag + (size_t)(row0 + r2) * Kdim + k0 + cc * 8);
            rb1 = *(const uint4*)(Bg + (size_t)(col0 + r1) * Kdim + k0 + cc * 8);
            rb2 = *(const uint4*)(Bg + (size_t)(col0 + r2) * Kdim + k0 + cc * 8);
        }

        // compute on stage s
        const uint32_t As = sb + (uint32_t)s * (2 * GSTAGE);
        const uint32_t Bs = As + GSTAGE;
#pragma unroll
        for (int ks = 0; ks < 2; ks++) {
            uint32_t af[4][4], bf[2][4];
#pragma unroll
            for (int mt = 0; mt < 4; mt++) {
                uint32_t addr = As + (a_lrow + (uint32_t)(mt * 16)) * 80u
                                   + (a_lk + (uint32_t)(ks * 16)) * 2u;
                LDSM_X4(af[mt][0], af[mt][1], af[mt][2], af[mt][3], addr);
            }
#pragma unroll
            for (int np = 0; np < 2; np++) {
                uint32_t addr = Bs + (b_lrow + (uint32_t)(np * 16)) * 80u
                                   + (b_lk + (uint32_t)(ks * 16)) * 2u;
                LDSM_X4(bf[np][0], bf[np][1], bf[np][2], bf[np][3], addr);
            }
#pragma unroll
            for (int mt = 0; mt < 4; mt++)
#pragma unroll
                for (int nt = 0; nt < 4; nt++) {
                    const uint32_t* bp = &bf[nt >> 1][(nt & 1) * 2];
                    MMA16816(acc[mt][nt], af[mt], bp[0], bp[1]);
                }
        }

        if (c + 1 < NC) {   // store next chunk into the other stage
            const uint32_t off = (uint32_t)((c + 1) & 1) * (2 * GSTAGE);
            *(uint4*)(smem + off + so1)          = ra1;
            *(uint4*)(smem + off + so2)          = ra2;
            *(uint4*)(smem + off + GSTAGE + so1) = rb1;
            *(uint4*)(smem + off + GSTAGE + so2) = rb2;
        }
    }

    // Epilogue: write accumulators
    const int erow = row0 + wm * 64 + (l >> 2);
    const int ecol = col0 + wn * 32 + 2 * (l & 3);
#pragma unroll
    for (int mt = 0; mt < 4; mt++)
#pragma unroll
        for (int nt = 0; nt < 4; nt++) {
            float2 v0 = {acc[mt][nt][0], acc[mt][nt][1]};
            float2 v1 = {acc[mt][nt][2], acc[mt][nt][3]};
            *(float2*)(C + (size_t)(erow + mt * 16)     * Ndim + ecol + nt * 8) = v0;
            *(float2*)(C + (size_t)(erow + mt * 16 + 8) * Ndim + ecol + nt * 8) = v1;
        }
}

// ---------------------------------------------------------------------------
// fp32 -> (hi, lo) bf16 split, elementwise. n4 = n/4.
// ---------------------------------------------------------------------------
__device__ __forceinline__ uint32_t pack_bf2(__nv_bfloat16 a, __nv_bfloat16 b) {
    return (uint32_t)__bfloat16_as_ushort(a) | ((uint32_t)__bfloat16_as_ushort(b) << 16);
}

__global__ __launch_bounds__(256) void split_kernel(
    const float* __restrict__ in, __nv_bfloat16* __restrict__ hi,
    __nv_bfloat16* __restrict__ lo, int n4)
{
    int i = blockIdx.x * blockDim.x + threadIdx.x;
    if (i >= n4) return;
    float4 v = ((const float4*)in)[i];
    float f[4] = {v.x, v.y, v.z, v.w};
    __nv_bfloat16 h[4], lw[4];
#pragma unroll
    for (int j = 0; j < 4; j++) {
        h[j]  = __float2bfloat16(f[j]);
        lw[j] = __float2bfloat16(f[j] - __bfloat162float(h[j]));
    }
    uint2 ph = {pack_bf2(h[0], h[1]), pack_bf2(h[2], h[3])};
    uint2 pl = {pack_bf2(lw[0], lw[1]), pack_bf2(lw[2], lw[3])};
    ((uint2*)hi)[i] = ph;
    ((uint2*)lo)[i] = pl;
}

// ---------------------------------------------------------------------------
// fp32 [R][C] -> transposed bf16 hi/lo [C][R] (weights: W[K][N] -> Wt[N][K])
// ---------------------------------------------------------------------------
__global__ void tsplit_kernel(const float* __restrict__ in,
                              __nv_bfloat16* __restrict__ hiT,
                              __nv_bfloat16* __restrict__ loT, int R, int Cc)
{
    __shared__ float sm2[32][33];
    int c0 = blockIdx.x * 32, r0 = blockIdx.y * 32;
    int tx = threadIdx.x, ty = threadIdx.y;
#pragma unroll
    for (int i = ty; i < 32; i += 8)
        sm2[i][tx] = in[(size_t)(r0 + i) * Cc + c0 + tx];
    __syncthreads();
#pragma unroll
    for (int i = ty; i < 32; i += 8) {
        float v = sm2[tx][i];                    // = in[r0+tx][c0+i]
        __nv_bfloat16 h = __float2bfloat16(v);
        __nv_bfloat16 lo = __float2bfloat16(v - __bfloat162float(h));
        size_t o = (size_t)(c0 + i) * R + r0 + tx;
        hiT[o] = h; loT[o] = lo;
    }
}

// ---------------------------------------------------------------------------
// Causal flash attention, fp32 (unchanged from R1).
// ---------------------------------------------------------------------------
#define ATTN_SMEM_FLOATS (64*132 + 64*68 + 64*68 + 64*132)

__global__ __launch_bounds__(256) void attn_kernel(
    const float* __restrict__ qkv, float* __restrict__ out)
{
    extern __shared__ float sm[];
    float* Qt = sm;                      // [d][i]  64 x 132
    float* Kt = Qt + 64 * 132;           // [d][j]  64 x 68
    float* Vs = Kt + 64 * 68;            // [j][d]  64 x 68
    float* Ps = Vs + 64 * 68;            // [j][i]  64 x 132

    const int t  = threadIdx.x;
    const int ty = t >> 4;
    const int tx = t & 15;
    const int qt = blockIdx.x;
    const int h  = blockIdx.y;
    const int b  = blockIdx.z;
    const int q0 = qt * 128;
    const float scale = 0.125f;

    {
        const float* qb = qkv + (size_t)(b * S_ + q0) * 3072 + h * HD_;
#pragma unroll
        for (int r = 0; r < 8; r++) {
            int idx = r * 256 + t;
            int i   = idx >> 4;
            int d4  = (idx & 15) * 4;
            float4 v = *(const float4*)(qb + (size_t)i * 3072 + d4);
            Qt[(d4 + 0) * 132 + i] = v.x * scale;
            Qt[(d4 + 1) * 132 + i] = v.y * scale;
            Qt[(d4 + 2) * 132 + i] = v.z * scale;
            Qt[(d4 + 3) * 132 + i] = v.w * scale;
        }
    }

    float mrow[8], lrow[8], O[8][4];
#pragma unroll
    for (int i = 0; i < 8; i++) {
        mrow[i] = -INFINITY; lrow[i] = 0.0f;
#pragma unroll
        for (int j = 0; j < 4; j++) O[i][j] = 0.0f;
    }

    const int ktiles = 2 * qt + 2;
    for (int kt = 0; kt < ktiles; kt++) {
        __syncthreads();
        const int k0 = kt * 64;
        {
            const float* kb = qkv + (size_t)(b * S_ + k0) * 3072 + 1024 + h * HD_;
            const float* vb = kb + 1024;
#pragma unroll
            for (int r = 0; r < 4; r++) {
                int idx = r * 256 + t;
                int j   = idx >> 4;
                int d4  = (idx & 15) * 4;
                float4 kv = *(const float4*)(kb + (size_t)j * 3072 + d4);
                Kt[(d4 + 0) * 68 + j] = kv.x;
                Kt[(d4 + 1) * 68 + j] = kv.y;
                Kt[(d4 + 2) * 68 + j] = kv.z;
                Kt[(d4 + 3) * 68 + j] = kv.w;
                float4 vv = *(const float4*)(vb + (size_t)j * 3072 + d4);
                *(float4*)&Vs[j * 68 + d4] = vv;
            }
        }
        __syncthreads();

        float Sv[8][4];
#pragma unroll
        for (int i = 0; i < 8; i++)
#pragma unroll
            for (int j = 0; j < 4; j++) Sv[i][j] = 0.0f;

#pragma unroll 4
        for (int d = 0; d < 64; d++) {
            float4 qa  = *(float4*)&Qt[d * 132 + ty * 8];
            float4 qb2 = *(float4*)&Qt[d * 132 + ty * 8 + 4];
            float4 kf  = *(float4*)&Kt[d * 68 + tx * 4];
            float qv[8] = {qa.x,qa.y,qa.z,qa.w,qb2.x,qb2.y,qb2.z,qb2.w};
            float kv[4] = {kf.x,kf.y,kf.z,kf.w};
#pragma unroll
            for (int i = 0; i < 8; i++)
#pragma unroll
                for (int j = 0; j < 4; j++)
                    Sv[i][j] = fmaf(qv[i], kv[j], Sv[i][j]);
        }

        if (k0 + 63 > q0) {
#pragma unroll
            for (int i = 0; i < 8; i++) {
                int gi = q0 + ty * 8 + i;
#pragma unroll
                for (int j = 0; j < 4; j++) {
                    int gj = k0 + tx * 4 + j;
                    if (gj > gi) Sv[i][j] = -INFINITY;
                }
            }
        }

#pragma unroll
        for (int i = 0; i < 8; i++) {
            float mx = fmaxf(fmaxf(Sv[i][0], Sv[i][1]), fmaxf(Sv[i][2], Sv[i][3]));
#pragma unroll
            for (int o = 8; o >= 1; o >>= 1)
                mx = fmaxf(mx, __shfl_xor_sync(0xffffffffu, mx, o, 16));
            float mn = fmaxf(mrow[i], mx);
            float corr = __expf(mrow[i] - mn);
            mrow[i] = mn;
            float p0 = __expf(Sv[i][0] - mn);
            float p1 = __expf(Sv[i][1] - mn);
            float p2 = __expf(Sv[i][2] - mn);
            float p3 = __expf(Sv[i][3] - mn);
            float rs = p0 + p1 + p2 + p3;
#pragma unroll
            for (int o = 8; o >= 1; o >>= 1)
                rs += __shfl_xor_sync(0xffffffffu, rs, o, 16);
            lrow[i] = lrow[i] * corr + rs;
#pragma unroll
            for (int j = 0; j < 4; j++) O[i][j] *= corr;
            int ii = ty * 8 + i;
            Ps[(tx * 4 + 0) * 132 + ii] = p0;
            Ps[(tx * 4 + 1) * 132 + ii] = p1;
            Ps[(tx * 4 + 2) * 132 + ii] = p2;
            Ps[(tx * 4 + 3) * 132 + ii] = p3;
        }
        __syncthreads();

#pragma unroll 4
        for (int j = 0; j < 64; j++) {
            float4 pa = *(float4*)&Ps[j * 132 + ty * 8];
            float4 pb = *(float4*)&Ps[j * 132 + ty * 8 + 4];
            float4 vf = *(float4*)&Vs[j * 68 + tx * 4];
            float pv[8] = {pa.x,pa.y,pa.z,pa.w,pb.x,pb.y,pb.z,pb.w};
            float vv[4] = {vf.x,vf.y,vf.z,vf.w};
#pragma unroll
            for (int i = 0; i < 8; i++)
#pragma unroll
                for (int d = 0; d < 4; d++)
                    O[i][d] = fmaf(pv[i], vv[d], O[i][d]);
        }
    }

#pragma unroll
    for (int i = 0; i < 8; i++) {
        float inv = 1.0f / lrow[i];
        float4 o = {O[i][0] * inv, O[i][1] * inv, O[i][2] * inv, O[i][3] * inv};
        size_t row = (size_t)(b * S_ + q0 + ty * 8 + i);
        *(float4*)(out + row * D_ + h * HD_ + tx * 4) = o;
    }
}

// ---------------------------------------------------------------------------
extern "C" void kernel_launch(void* const* d_in, const int* in_sizes, int n_in,
                              void* d_out, int out_size)
{
    const float* x = nullptr; const float* wqkv = nullptr; const float* wout = nullptr;
    for (int i = 0; i < n_in; i++) {
        if (in_sizes[i] == 8388608)      x    = (const float*)d_in[i];
        else if (in_sizes[i] == 3145728) wqkv = (const float*)d_in[i];
        else if (in_sizes[i] == 1048576) wout = (const float*)d_in[i];
    }
    float* out = (float*)d_out;

    void* p;
    cudaGetSymbolAddress(&p, g_qkv);      float* qkv  = (float*)p;
    cudaGetSymbolAddress(&p, g_attn);     float* attn = (float*)p;
    cudaGetSymbolAddress(&p, g_x_hi);     __nv_bfloat16* x_hi = (__nv_bfloat16*)p;
    cudaGetSymbolAddress(&p, g_x_lo);     __nv_bfloat16* x_lo = (__nv_bfloat16*)p;
    cudaGetSymbolAddress(&p, g_attn_hi);  __nv_bfloat16* a_hi = (__nv_bfloat16*)p;
    cudaGetSymbolAddress(&p, g_attn_lo);  __nv_bfloat16* a_lo = (__nv_bfloat16*)p;
    cudaGetSymbolAddress(&p, g_wqkvT_hi); __nv_bfloat16* wq_hi = (__nv_bfloat16*)p;
    cudaGetSymbolAddress(&p, g_wqkvT_lo); __nv_bfloat16* wq_lo = (__nv_bfloat16*)p;
    cudaGetSymbolAddress(&p, g_woutT_hi); __nv_bfloat16* wo_hi = (__nv_bfloat16*)p;
    cudaGetSymbolAddress(&p, g_woutT_lo); __nv_bfloat16* wo_lo = (__nv_bfloat16*)p;

    cudaFuncSetAttribute(attn_kernel, cudaFuncAttributeMaxDynamicSharedMemorySize,
                         ATTN_SMEM_FLOATS * (int)sizeof(float));
    cudaFuncSetAttribute(gemm_mma_kernel, cudaFuncAttributeMaxDynamicSharedMemorySize,
                         GEMM_SMEM_BYTES);

    // Weight split+transpose: W[K][N] -> Wt[N][K] hi/lo bf16
    tsplit_kernel<<<dim3(3 * D_ / 32, D_ / 32), dim3(32, 8)>>>(wqkv, wq_hi, wq_lo, D_, 3 * D_);
    tsplit_kernel<<<dim3(D_ / 32, D_ / 32), dim3(32, 8)>>>(wout, wo_hi, wo_lo, D_, D_);
    // x split
    split_kernel<<<(M_ * D_ / 4 + 255) / 256, 256>>>(x, x_hi, x_lo, M_ * D_ / 4);

    // 1) qkv = x @ W_qkv   (mma.sync bf16x3)
    gemm_mma_kernel<<<dim3(3 * D_ / 128, M_ / 128), 256, GEMM_SMEM_BYTES>>>(
        x_hi, x_lo, wq_hi, wq_lo, qkv, 3 * D_, D_);

    // 2) attention (fp32 FFMA)
    attn_kernel<<<dim3(S_ / 128, H_, B_), 256, ATTN_SMEM_FLOATS * sizeof(float)>>>(qkv, attn);

    // attn split
    split_kernel<<<(M_ * D_ / 4 + 255) / 256, 256>>>(attn, a_hi, a_lo, M_ * D_ / 4);

    // 3) out = attn @ W_out   (mma.sync bf16x3)
    gemm_mma_kernel<<<dim3(D_ / 128, M_ / 128), 256, GEMM_SMEM_BYTES>>>(
        a_hi, a_lo, wo_hi, wo_lo, out, D_, D_);
}

// round 8
// speedup vs baseline: 2.0019x; 1.3782x over previous
#include <cuda_runtime.h>
#include <cuda_bf16.h>
#include <math.h>
#include <cstdint>

// Problem constants
#define B_  4
#define S_  2048
#define D_  1024
#define H_  16
#define HD_ 64
#define M_  (B_ * S_)        // 8192 rows

// Scratch buffers
__device__ __nv_bfloat16 g_qkvh[(size_t)M_ * 3 * D_];   // [8192][3072]
__device__ __nv_bfloat16 g_qkvl[(size_t)M_ * 3 * D_];
__device__ __nv_bfloat16 g_x_hi[(size_t)M_ * D_];
__device__ __nv_bfloat16 g_x_lo[(size_t)M_ * D_];
__device__ __nv_bfloat16 g_attn_hi[(size_t)M_ * D_];
__device__ __nv_bfloat16 g_attn_lo[(size_t)M_ * D_];
__device__ __nv_bfloat16 g_wqkvT_hi[(size_t)3 * D_ * D_];   // [3072][1024]
__device__ __nv_bfloat16 g_wqkvT_lo[(size_t)3 * D_ * D_];
__device__ __nv_bfloat16 g_woutT_hi[(size_t)D_ * D_];       // [1024][1024]
__device__ __nv_bfloat16 g_woutT_lo[(size_t)D_ * D_];

// ---------------------------------------------------------------------------
// PTX helpers (baseline PTX only: ldmatrix, mma.sync, cp.async)
// ---------------------------------------------------------------------------
__device__ __forceinline__ uint32_t smem_u32(const void* p) {
    uint32_t a;
    asm("{ .reg .u64 t; cvta.to.shared.u64 t, %1; cvt.u32.u64 %0, t; }" : "=r"(a) : "l"(p));
    return a;
}
__device__ __forceinline__ void cpa16(uint32_t s, const void* g) {
    asm volatile("cp.async.cg.shared.global [%0], [%1], 16;" :: "r"(s), "l"(g));
}
#define CPA_COMMIT() asm volatile("cp.async.commit_group;" ::: "memory")
#define CPA_WAIT(n)  asm volatile("cp.async.wait_group %0;" :: "n"(n) : "memory")

#define LDSM_X4(r0, r1, r2, r3, addr) \
    asm volatile("ldmatrix.sync.aligned.m8n8.x4.shared.b16 {%0,%1,%2,%3}, [%4];" \
                 : "=r"(r0), "=r"(r1), "=r"(r2), "=r"(r3) : "r"(addr))
#define LDSM_X4T(r0, r1, r2, r3, addr) \
    asm volatile("ldmatrix.sync.aligned.m8n8.x4.trans.shared.b16 {%0,%1,%2,%3}, [%4];" \
                 : "=r"(r0), "=r"(r1), "=r"(r2), "=r"(r3) : "r"(addr))

#define MMA16816(d, a, bb0, bb1) \
    asm volatile("mma.sync.aligned.m16n8k16.row.col.f32.bf16.bf16.f32 " \
                 "{%0,%1,%2,%3}, {%4,%5,%6,%7}, {%8,%9}, {%0,%1,%2,%3};" \
                 : "+f"((d)[0]), "+f"((d)[1]), "+f"((d)[2]), "+f"((d)[3]) \
                 : "r"((a)[0]), "r"((a)[1]), "r"((a)[2]), "r"((a)[3]), \
                   "r"(bb0), "r"(bb1))

__device__ __forceinline__ uint32_t pack_hi2(float a, float b) {
    return (uint32_t)__bfloat16_as_ushort(__float2bfloat16(a))
         | ((uint32_t)__bfloat16_as_ushort(__float2bfloat16(b)) << 16);
}
__device__ __forceinline__ uint32_t pack_lo2(float a, float b) {
    __nv_bfloat16 ha = __float2bfloat16(a), hb = __float2bfloat16(b);
    __nv_bfloat16 la = __float2bfloat16(a - __bfloat162float(ha));
    __nv_bfloat16 lb = __float2bfloat16(b - __bfloat162float(hb));
    return (uint32_t)__bfloat16_as_ushort(la) | ((uint32_t)__bfloat16_as_ushort(lb) << 16);
}

// ---------------------------------------------------------------------------
// bf16 split-3 GEMM via mma.sync + cp.async double-buffer.
// C = Ahi*Bhi + Ahi*Blo + Alo*Bhi.  A [M][K], B [N][K] (weights transposed).
// Tile 128x128, BK=32, 256 threads (8 warps 2x4, warp tile 64x32).
// Output: fp32 (Cf) OR bf16 hi/lo (Ch/Cl) if Cf==nullptr.
// ---------------------------------------------------------------------------
#define GPITCH 40
#define GSTAGE (128 * GPITCH * 2)         // 10240 B
#define GEMM_SMEM_BYTES (4 * GSTAGE)      // 40960 B

__global__ __launch_bounds__(256, 2)
void gemm_mma_kernel(const __nv_bfloat16* __restrict__ Ahi, const __nv_bfloat16* __restrict__ Alo,
                     const __nv_bfloat16* __restrict__ Bhi, const __nv_bfloat16* __restrict__ Blo,
                     float* __restrict__ Cf, __nv_bfloat16* __restrict__ Ch,
                     __nv_bfloat16* __restrict__ Cl, int Ndim, int Kdim)
{
    extern __shared__ __align__(16) char smem[];
    const uint32_t sb = smem_u32(smem);

    const int t   = threadIdx.x;
    const int l   = t & 31;
    const int wid = t >> 5;
    const int wm  = wid >> 2;
    const int wn  = wid & 3;
    const int row0 = blockIdx.y * 128, col0 = blockIdx.x * 128;

    const __nv_bfloat16* Ap[3] = {Ahi, Ahi, Alo};
    const __nv_bfloat16* Bp[3] = {Bhi, Blo, Bhi};
    const int KCH = Kdim >> 5;
    const int NC  = 3 * KCH;

    const int r1 = t >> 2, cc = t & 3;
    const int r2 = 64 + r1;
    const uint32_t so1 = (uint32_t)(r1 * 80 + cc * 16);
    const uint32_t so2 = (uint32_t)(r2 * 80 + cc * 16);

    float acc[4][4][4];
#pragma unroll
    for (int i = 0; i < 4; i++)
#pragma unroll
        for (int j = 0; j < 4; j++)
#pragma unroll
            for (int k = 0; k < 4; k++) acc[i][j][k] = 0.0f;

    // issue stage for chunk c
    auto issue = [&](int c) {
        const int pidx = c / KCH;
        const int k0 = (c - pidx * KCH) << 5;
        const uint32_t base = sb + (uint32_t)(c & 1) * (2 * GSTAGE);
        const __nv_bfloat16* Ag = Ap[pidx];
        const __nv_bfloat16* Bg = Bp[pidx];
        cpa16(base + so1,          Ag + (size_t)(row0 + r1) * Kdim + k0 + cc * 8);
        cpa16(base + so2,          Ag + (size_t)(row0 + r2) * Kdim + k0 + cc * 8);
        cpa16(base + GSTAGE + so1, Bg + (size_t)(col0 + r1) * Kdim + k0 + cc * 8);
        cpa16(base + GSTAGE + so2, Bg + (size_t)(col0 + r2) * Kdim + k0 + cc * 8);
        CPA_COMMIT();
    };

    issue(0);

    const uint32_t a_lrow = (uint32_t)(wm * 64 + (l & 15));
    const uint32_t a_lk   = (uint32_t)((l >> 4) * 8);
    const uint32_t b_lrow = (uint32_t)(wn * 32 + ((l >> 4) & 1) * 8 + (l & 7));
    const uint32_t b_lk   = (uint32_t)(((l >> 3) & 1) * 8);

    for (int c = 0; c < NC; c++) {
        if (c + 1 < NC) { issue(c + 1); CPA_WAIT(1); }
        else            { CPA_WAIT(0); }
        __syncthreads();

        const uint32_t As = sb + (uint32_t)(c & 1) * (2 * GSTAGE);
        const uint32_t Bs = As + GSTAGE;
#pragma unroll
        for (int ks = 0; ks < 2; ks++) {
            uint32_t af[4][4], bf[2][4];
#pragma unroll
            for (int mt = 0; mt < 4; mt++) {
                uint32_t addr = As + (a_lrow + (uint32_t)(mt * 16)) * 80u
                                   + (a_lk + (uint32_t)(ks * 16)) * 2u;
                LDSM_X4(af[mt][0], af[mt][1], af[mt][2], af[mt][3], addr);
            }
#pragma unroll
            for (int np = 0; np < 2; np++) {
                uint32_t addr = Bs + (b_lrow + (uint32_t)(np * 16)) * 80u
                                   + (b_lk + (uint32_t)(ks * 16)) * 2u;
                LDSM_X4(bf[np][0], bf[np][1], bf[np][2], bf[np][3], addr);
            }
#pragma unroll
            for (int mt = 0; mt < 4; mt++)
#pragma unroll
                for (int nt = 0; nt < 4; nt++) {
                    const uint32_t* bp = &bf[nt >> 1][(nt & 1) * 2];
                    MMA16816(acc[mt][nt], af[mt], bp[0], bp[1]);
                }
        }
        __syncthreads();
    }

    // Epilogue
    const int erow = row0 + wm * 64 + (l >> 2);
    const int ecol = col0 + wn * 32 + 2 * (l & 3);
    if (Cf) {
#pragma unroll
        for (int mt = 0; mt < 4; mt++)
#pragma unroll
            for (int nt = 0; nt < 4; nt++) {
                float2 v0 = {acc[mt][nt][0], acc[mt][nt][1]};
                float2 v1 = {acc[mt][nt][2], acc[mt][nt][3]};
                *(float2*)(Cf + (size_t)(erow + mt * 16)     * Ndim + ecol + nt * 8) = v0;
                *(float2*)(Cf + (size_t)(erow + mt * 16 + 8) * Ndim + ecol + nt * 8) = v1;
            }
    } else {
#pragma unroll
        for (int mt = 0; mt < 4; mt++)
#pragma unroll
            for (int nt = 0; nt < 4; nt++) {
                size_t o0 = (size_t)(erow + mt * 16)     * Ndim + ecol + nt * 8;
                size_t o1 = (size_t)(erow + mt * 16 + 8) * Ndim + ecol + nt * 8;
                *(uint32_t*)(Ch + o0) = pack_hi2(acc[mt][nt][0], acc[mt][nt][1]);
                *(uint32_t*)(Cl + o0) = pack_lo2(acc[mt][nt][0], acc[mt][nt][1]);
                *(uint32_t*)(Ch + o1) = pack_hi2(acc[mt][nt][2], acc[mt][nt][3]);
                *(uint32_t*)(Cl + o1) = pack_lo2(acc[mt][nt][2], acc[mt][nt][3]);
            }
    }
}

// ---------------------------------------------------------------------------
// fp32 -> (hi, lo) bf16 split (for x input)
// ---------------------------------------------------------------------------
__global__ __launch_bounds__(256) void split_kernel(
    const float* __restrict__ in, __nv_bfloat16* __restrict__ hi,
    __nv_bfloat16* __restrict__ lo, int n4)
{
    int i = blockIdx.x * blockDim.x + threadIdx.x;
    if (i >= n4) return;
    float4 v = ((const float4*)in)[i];
    uint2 ph = {pack_hi2(v.x, v.y), pack_hi2(v.z, v.w)};
    uint2 pl = {pack_lo2(v.x, v.y), pack_lo2(v.z, v.w)};
    ((uint2*)hi)[i] = ph;
    ((uint2*)lo)[i] = pl;
}

// ---------------------------------------------------------------------------
// fp32 [R][C] -> transposed bf16 hi/lo [C][R]
// ---------------------------------------------------------------------------
__global__ void tsplit_kernel(const float* __restrict__ in,
                              __nv_bfloat16* __restrict__ hiT,
                              __nv_bfloat16* __restrict__ loT, int R, int Cc)
{
    __shared__ float sm2[32][33];
    int c0 = blockIdx.x * 32, r0 = blockIdx.y * 32;
    int tx = threadIdx.x, ty = threadIdx.y;
#pragma unroll
    for (int i = ty; i < 32; i += 8)
        sm2[i][tx] = in[(size_t)(r0 + i) * Cc + c0 + tx];
    __syncthreads();
#pragma unroll
    for (int i = ty; i < 32; i += 8) {
        float v = sm2[tx][i];
        __nv_bfloat16 h = __float2bfloat16(v);
        __nv_bfloat16 lo = __float2bfloat16(v - __bfloat162float(h));
        size_t o = (size_t)(c0 + i) * R + r0 + tx;
        hiT[o] = h; loT[o] = lo;
    }
}

// ---------------------------------------------------------------------------
// Causal flash attention via mma.sync, bf16 split-3 in both GEMMs.
// Inputs: qkv hi/lo [row][3072] (Q at h*64, K at 1024+h*64, V at 2048+h*64).
// Output: attn hi/lo [row][1024].
// Block: 256 thr (8 warps); warp w owns q-rows w*16..+16 of a 128-row tile.
// k-loop: BN=64 keys/tile, causal skip.
// Smem (pitch 72 elems = 144B, conflict-free ldsm):
//   Qh[128], Ql[128], Kh[64], Kl[64], Vh[64], Vl[64]  -> 73728 B
// ---------------------------------------------------------------------------
#define AP  72
#define APB 144
#define AQ_OFF  0
#define AQL_OFF (128 * APB)                 // 18432
#define AKH_OFF (2 * 128 * APB)             // 36864
#define AKL_OFF (AKH_OFF + 64 * APB)        // 46080
#define AVH_OFF (AKL_OFF + 64 * APB)        // 55296
#define AVL_OFF (AVH_OFF + 64 * APB)        // 64512
#define ATTN_SMEM_BYTES (AVL_OFF + 64 * APB) // 73728

__global__ __launch_bounds__(256, 2)
void attn_mma_kernel(const __nv_bfloat16* __restrict__ qkvh,
                     const __nv_bfloat16* __restrict__ qkvl,
                     __nv_bfloat16* __restrict__ outh,
                     __nv_bfloat16* __restrict__ outl)
{
    extern __shared__ __align__(16) char smem[];
    const uint32_t sb = smem_u32(smem);

    const int t = threadIdx.x, l = t & 31, w = t >> 5;
    const int qt = blockIdx.x, h = blockIdx.y, b = blockIdx.z;
    const int q0 = qt * 128;

    // Q tile load (hi+lo), 128 rows x 64 cols
    {
#pragma unroll
        for (int i = 0; i < 4; i++) {
            int q = t + i * 256;                 // 0..1023
            int r = q >> 3, ch = q & 7;
            size_t g = (size_t)(b * S_ + q0 + r) * 3072 + h * HD_ + ch * 8;
            uint32_t s = (uint32_t)(r * APB + ch * 16);
            cpa16(sb + AQ_OFF + s,  qkvh + g);
            cpa16(sb + AQL_OFF + s, qkvl + g);
        }
        CPA_COMMIT();
    }

    float m0 = -INFINITY, m1 = -INFINITY, lr0 = 0.0f, lr1 = 0.0f;
    float O[8][4];
#pragma unroll
    for (int n = 0; n < 8; n++)
#pragma unroll
        for (int k = 0; k < 4; k++) O[n][k] = 0.0f;

    // ldsm lane offsets
    const uint32_t a_row = (uint32_t)(w * 16 + (l & 15));        // Q rows
    const uint32_t a_kd  = (uint32_t)((l >> 4) * 8);             // Q d
    const uint32_t bk_j  = (uint32_t)(((l >> 4) & 1) * 8 + (l & 7));
    const uint32_t bk_d  = (uint32_t)(((l >> 3) & 1) * 8);
    const uint32_t bv_j  = (uint32_t)(((l >> 3) & 1) * 8 + (l & 7));
    const uint32_t bv_d  = (uint32_t)((l >> 4) * 8);

    const int ktiles = 2 * qt + 2;
    for (int kt = 0; kt < ktiles; kt++) {
        const int k0 = kt * 64;
        __syncthreads();    // previous tile's compute done before overwrite
        // K/V hi/lo loads (64 rows x 64 cols each)
#pragma unroll
        for (int i = 0; i < 2; i++) {
            int q = t + i * 256;                 // 0..511
            int r = q >> 3, ch = q & 7;
            size_t gk = (size_t)(b * S_ + k0 + r) * 3072 + 1024 + h * HD_ + ch * 8;
            size_t gv = gk + 1024;
            uint32_t s = (uint32_t)(r * APB + ch * 16);
            cpa16(sb + AKH_OFF + s, qkvh + gk);
            cpa16(sb + AKL_OFF + s, qkvl + gk);
            cpa16(sb + AVH_OFF + s, qkvh + gv);
            cpa16(sb + AVL_OFF + s, qkvl + gv);
        }
        CPA_COMMIT();
        CPA_WAIT(0);
        __syncthreads();

        // ---- S = Q K^T (3 passes: QhKh, QhKl, QlKh), fp32 accum ----
        float S[8][4];
#pragma unroll
        for (int n = 0; n < 8; n++)
#pragma unroll
            for (int k = 0; k < 4; k++) S[n][k] = 0.0f;

#pragma unroll
        for (int pass = 0; pass < 3; pass++) {
            const uint32_t qb = sb + (pass == 2 ? AQL_OFF : AQ_OFF);
            const uint32_t kb = sb + (pass == 1 ? AKL_OFF : AKH_OFF);
#pragma unroll
            for (int ks = 0; ks < 4; ks++) {
                uint32_t aq[4];
                LDSM_X4(aq[0], aq[1], aq[2], aq[3],
                        qb + a_row * APB + (a_kd + (uint32_t)(ks * 16)) * 2u);
#pragma unroll
                for (int jp = 0; jp < 4; jp++) {
                    uint32_t bk[4];
                    LDSM_X4(bk[0], bk[1], bk[2], bk[3],
                            kb + (bk_j + (uint32_t)(jp * 16)) * APB
                               + (bk_d + (uint32_t)(ks * 16)) * 2u);
                    MMA16816(S[2 * jp],     aq, bk[0], bk[1]);
                    MMA16816(S[2 * jp + 1], aq, bk[2], bk[3]);
                }
            }
        }

        // scale
#pragma unroll
        for (int n = 0; n < 8; n++)
#pragma unroll
            for (int k = 0; k < 4; k++) S[n][k] *= 0.125f;

        // causal mask (diagonal tiles only)
        if (kt >= 2 * qt) {
            const int gi0 = q0 + w * 16 + (l >> 2);
            const int gi1 = gi0 + 8;
#pragma unroll
            for (int n = 0; n < 8; n++) {
                const int gj = k0 + n * 8 + (l & 3) * 2;
                if (gj     > gi0) S[n][0] = -INFINITY;
                if (gj + 1 > gi0) S[n][1] = -INFINITY;
                if (gj     > gi1) S[n][2] = -INFINITY;
                if (gj + 1 > gi1) S[n][3] = -INFINITY;
            }
        }

        // ---- online softmax ----
        float mx0 = -INFINITY, mx1 = -INFINITY;
#pragma unroll
        for (int n = 0; n < 8; n++) {
            mx0 = fmaxf(mx0, fmaxf(S[n][0], S[n][1]));
            mx1 = fmaxf(mx1, fmaxf(S[n][2], S[n][3]));
        }
        mx0 = fmaxf(mx0, __shfl_xor_sync(0xffffffffu, mx0, 1));
        mx0 = fmaxf(mx0, __shfl_xor_sync(0xffffffffu, mx0, 2));
        mx1 = fmaxf(mx1, __shfl_xor_sync(0xffffffffu, mx1, 1));
        mx1 = fmaxf(mx1, __shfl_xor_sync(0xffffffffu, mx1, 2));
        const float mn0 = fmaxf(m0, mx0), mn1 = fmaxf(m1, mx1);
        const float corr0 = __expf(m0 - mn0), corr1 = __expf(m1 - mn1);
        m0 = mn0; m1 = mn1;
        float sum0 = 0.0f, sum1 = 0.0f;
#pragma unroll
        for (int n = 0; n < 8; n++) {
            S[n][0] = __expf(S[n][0] - mn0);
            S[n][1] = __expf(S[n][1] - mn0);
            S[n][2] = __expf(S[n][2] - mn1);
            S[n][3] = __expf(S[n][3] - mn1);
            sum0 += S[n][0] + S[n][1];
            sum1 += S[n][2] + S[n][3];
            O[n][0] *= corr0; O[n][1] *= corr0;
            O[n][2] *= corr1; O[n][3] *= corr1;
        }
        sum0 += __shfl_xor_sync(0xffffffffu, sum0, 1);
        sum0 += __shfl_xor_sync(0xffffffffu, sum0, 2);
        sum1 += __shfl_xor_sync(0xffffffffu, sum1, 1);
        sum1 += __shfl_xor_sync(0xffffffffu, sum1, 2);
        lr0 = lr0 * corr0 + sum0;
        lr1 = lr1 * corr1 + sum1;

        // ---- O += P V (3 passes: PhVh, PhVl, PlVh) ----
        uint32_t pf[16];
#pragma unroll
        for (int ks = 0; ks < 4; ks++) {
            pf[ks * 4 + 0] = pack_hi2(S[2 * ks][0],     S[2 * ks][1]);
            pf[ks * 4 + 1] = pack_hi2(S[2 * ks][2],     S[2 * ks][3]);
            pf[ks * 4 + 2] = pack_hi2(S[2 * ks + 1][0], S[2 * ks + 1][1]);
            pf[ks * 4 + 3] = pack_hi2(S[2 * ks + 1][2], S[2 * ks + 1][3]);
        }
#pragma unroll
        for (int pass = 0; pass < 3; pass++) {
            if (pass == 2) {
#pragma unroll
                for (int ks = 0; ks < 4; ks++) {
                    pf[ks * 4 + 0] = pack_lo2(S[2 * ks][0],     S[2 * ks][1]);
                    pf[ks * 4 + 1] = pack_lo2(S[2 * ks][2],     S[2 * ks][3]);
                    pf[ks * 4 + 2] = pack_lo2(S[2 * ks + 1][0], S[2 * ks + 1][1]);
                    pf[ks * 4 + 3] = pack_lo2(S[2 * ks + 1][2], S[2 * ks + 1][3]);
                }
            }
            const uint32_t vb = sb + (pass == 1 ? AVL_OFF : AVH_OFF);
#pragma unroll
            for (int ks = 0; ks < 4; ks++) {
#pragma unroll
                for (int np = 0; np < 4; np++) {
                    uint32_t bv[4];
                    LDSM_X4T(bv[0], bv[1], bv[2], bv[3],
                             vb + (bv_j + (uint32_t)(ks * 16)) * APB
                                + (bv_d + (uint32_t)(np * 16)) * 2u);
                    MMA16816(O[2 * np],     &pf[ks * 4], bv[0], bv[1]);
                    MMA16816(O[2 * np + 1], &pf[ks * 4], bv[2], bv[3]);
                }
            }
        }
    }

    // ---- epilogue: normalize, write bf16 hi/lo ----
    const float inv0 = 1.0f / lr0, inv1 = 1.0f / lr1;
    const size_t row0g = (size_t)(b * S_ + q0 + w * 16 + (l >> 2));
    const size_t row1g = row0g + 8;
#pragma unroll
    for (int n = 0; n < 8; n++) {
        const int d0 = h * HD_ + n * 8 + (l & 3) * 2;
        float v0 = O[n][0] * inv0, v1 = O[n][1] * inv0;
        float v2 = O[n][2] * inv1, v3 = O[n][3] * inv1;
        *(uint32_t*)(outh + row0g * D_ + d0) = pack_hi2(v0, v1);
        *(uint32_t*)(outl + row0g * D_ + d0) = pack_lo2(v0, v1);
        *(uint32_t*)(outh + row1g * D_ + d0) = pack_hi2(v2, v3);
        *(uint32_t*)(outl + row1g * D_ + d0) = pack_lo2(v2, v3);
    }
}

// ---------------------------------------------------------------------------
extern "C" void kernel_launch(void* const* d_in, const int* in_sizes, int n_in,
                              void* d_out, int out_size)
{
    const float* x = nullptr; const float* wqkv = nullptr; const float* wout = nullptr;
    for (int i = 0; i < n_in; i++) {
        if (in_sizes[i] == 8388608)      x    = (const float*)d_in[i];
        else if (in_sizes[i] == 3145728) wqkv = (const float*)d_in[i];
        else if (in_sizes[i] == 1048576) wout = (const float*)d_in[i];
    }
    float* out = (float*)d_out;

    void* p;
    cudaGetSymbolAddress(&p, g_qkvh);     __nv_bfloat16* qkvh = (__nv_bfloat16*)p;
    cudaGetSymbolAddress(&p, g_qkvl);     __nv_bfloat16* qkvl = (__nv_bfloat16*)p;
    cudaGetSymbolAddress(&p, g_x_hi);     __nv_bfloat16* x_hi = (__nv_bfloat16*)p;
    cudaGetSymbolAddress(&p, g_x_lo);     __nv_bfloat16* x_lo = (__nv_bfloat16*)p;
    cudaGetSymbolAddress(&p, g_attn_hi);  __nv_bfloat16* a_hi = (__nv_bfloat16*)p;
    cudaGetSymbolAddress(&p, g_attn_lo);  __nv_bfloat16* a_lo = (__nv_bfloat16*)p;
    cudaGetSymbolAddress(&p, g_wqkvT_hi); __nv_bfloat16* wq_hi = (__nv_bfloat16*)p;
    cudaGetSymbolAddress(&p, g_wqkvT_lo); __nv_bfloat16* wq_lo = (__nv_bfloat16*)p;
    cudaGetSymbolAddress(&p, g_woutT_hi); __nv_bfloat16* wo_hi = (__nv_bfloat16*)p;
    cudaGetSymbolAddress(&p, g_woutT_lo); __nv_bfloat16* wo_lo = (__nv_bfloat16*)p;

    cudaFuncSetAttribute(gemm_mma_kernel, cudaFuncAttributeMaxDynamicSharedMemorySize,
                         GEMM_SMEM_BYTES);
    cudaFuncSetAttribute(attn_mma_kernel, cudaFuncAttributeMaxDynamicSharedMemorySize,
                         ATTN_SMEM_BYTES);

    // Weight split+transpose
    tsplit_kernel<<<dim3(3 * D_ / 32, D_ / 32), dim3(32, 8)>>>(wqkv, wq_hi, wq_lo, D_, 3 * D_);
    tsplit_kernel<<<dim3(D_ / 32, D_ / 32), dim3(32, 8)>>>(wout, wo_hi, wo_lo, D_, D_);
    // x split
    split_kernel<<<(M_ * D_ / 4 + 255) / 256, 256>>>(x, x_hi, x_lo, M_ * D_ / 4);

    // 1) qkv(hi/lo) = x @ W_qkv
    gemm_mma_kernel<<<dim3(3 * D_ / 128, M_ / 128), 256, GEMM_SMEM_BYTES>>>(
        x_hi, x_lo, wq_hi, wq_lo, nullptr, qkvh, qkvl, 3 * D_, D_);

    // 2) attention (mma.sync, split-3) -> attn hi/lo
    attn_mma_kernel<<<dim3(S_ / 128, H_, B_), 256, ATTN_SMEM_BYTES>>>(qkvh, qkvl, a_hi, a_lo);

    // 3) out = attn @ W_out  (fp32 out)
    gemm_mma_kernel<<<dim3(D_ / 128, M_ / 128), 256, GEMM_SMEM_BYTES>>>(
        a_hi, a_lo, wo_hi, wo_lo, out, nullptr, nullptr, D_, D_);
}

// round 9
// speedup vs baseline: 2.9417x; 1.4695x over previous
#include <cuda_runtime.h>
#include <cuda_bf16.h>
#include <math.h>
#include <cstdint>

// Problem constants
#define B_  4
#define S_  2048
#define D_  1024
#define H_  16
#define HD_ 64
#define M_  (B_ * S_)        // 8192 rows

// Scratch buffers
__device__ __nv_bfloat16 g_qkvh[(size_t)M_ * 3 * D_];   // [8192][3072]
__device__ __nv_bfloat16 g_qkvl[(size_t)M_ * 3 * D_];
__device__ __nv_bfloat16 g_x_hi[(size_t)M_ * D_];
__device__ __nv_bfloat16 g_x_lo[(size_t)M_ * D_];
__device__ __nv_bfloat16 g_attn_hi[(size_t)M_ * D_];
__device__ __nv_bfloat16 g_attn_lo[(size_t)M_ * D_];
__device__ __nv_bfloat16 g_wqkvT_hi[(size_t)3 * D_ * D_];   // [3072][1024]
__device__ __nv_bfloat16 g_wqkvT_lo[(size_t)3 * D_ * D_];
__device__ __nv_bfloat16 g_woutT_hi[(size_t)D_ * D_];       // [1024][1024]
__device__ __nv_bfloat16 g_woutT_lo[(size_t)D_ * D_];

// ---------------------------------------------------------------------------
// PTX helpers (baseline PTX only: ldmatrix, mma.sync, cp.async)
// ---------------------------------------------------------------------------
__device__ __forceinline__ uint32_t smem_u32(const void* p) {
    uint32_t a;
    asm("{ .reg .u64 t; cvta.to.shared.u64 t, %1; cvt.u32.u64 %0, t; }" : "=r"(a) : "l"(p));
    return a;
}
__device__ __forceinline__ void cpa16(uint32_t s, const void* g) {
    asm volatile("cp.async.cg.shared.global [%0], [%1], 16;" :: "r"(s), "l"(g));
}
#define CPA_COMMIT() asm volatile("cp.async.commit_group;" ::: "memory")
#define CPA_WAIT(n)  asm volatile("cp.async.wait_group %0;" :: "n"(n) : "memory")

#define LDSM_X4(r0, r1, r2, r3, addr) \
    asm volatile("ldmatrix.sync.aligned.m8n8.x4.shared.b16 {%0,%1,%2,%3}, [%4];" \
                 : "=r"(r0), "=r"(r1), "=r"(r2), "=r"(r3) : "r"(addr))
#define LDSM_X4T(r0, r1, r2, r3, addr) \
    asm volatile("ldmatrix.sync.aligned.m8n8.x4.trans.shared.b16 {%0,%1,%2,%3}, [%4];" \
                 : "=r"(r0), "=r"(r1), "=r"(r2), "=r"(r3) : "r"(addr))

#define MMA16816(d, a, bb0, bb1) \
    asm volatile("mma.sync.aligned.m16n8k16.row.col.f32.bf16.bf16.f32 " \
                 "{%0,%1,%2,%3}, {%4,%5,%6,%7}, {%8,%9}, {%0,%1,%2,%3};" \
                 : "+f"((d)[0]), "+f"((d)[1]), "+f"((d)[2]), "+f"((d)[3]) \
                 : "r"((a)[0]), "r"((a)[1]), "r"((a)[2]), "r"((a)[3]), \
                   "r"(bb0), "r"(bb1))

__device__ __forceinline__ uint32_t pack_hi2(float a, float b) {
    return (uint32_t)__bfloat16_as_ushort(__float2bfloat16(a))
         | ((uint32_t)__bfloat16_as_ushort(__float2bfloat16(b)) << 16);
}
__device__ __forceinline__ uint32_t pack_lo2(float a, float b) {
    __nv_bfloat16 ha = __float2bfloat16(a), hb = __float2bfloat16(b);
    __nv_bfloat16 la = __float2bfloat16(a - __bfloat162float(ha));
    __nv_bfloat16 lb = __float2bfloat16(b - __bfloat162float(hb));
    return (uint32_t)__bfloat16_as_ushort(la) | ((uint32_t)__bfloat16_as_ushort(lb) << 16);
}

// ---------------------------------------------------------------------------
// bf16 split-3 GEMM, pass-merged: each K-chunk loads Ahi/Alo/Bhi/Blo once and
// issues all 3 products into the same fp32 accumulators.
// C = Ahi*Bhi + Ahi*Blo + Alo*Bhi.  A [M][K], B [N][K] (weights transposed).
// Tile 128x128, BK=32, 256 threads (8 warps 2x4, warp tile 64x32).
// Output: fp32 (Cf) OR bf16 hi/lo (Ch/Cl) if Cf==nullptr.
// ---------------------------------------------------------------------------
#define GTILE 10240                        // one 128x32 bf16 tile (pitch 80B)
#define GSTG  (4 * GTILE)                  // Ahi,Alo,Bhi,Blo = 40960 B
#define GEMM_SMEM_BYTES (2 * GSTG)         // 81920 B

__global__ __launch_bounds__(256, 2)
void gemm_mma_kernel(const __nv_bfloat16* __restrict__ Ahi, const __nv_bfloat16* __restrict__ Alo,
                     const __nv_bfloat16* __restrict__ Bhi, const __nv_bfloat16* __restrict__ Blo,
                     float* __restrict__ Cf, __nv_bfloat16* __restrict__ Ch,
                     __nv_bfloat16* __restrict__ Cl, int Ndim, int Kdim)
{
    extern __shared__ __align__(16) char smem[];
    const uint32_t sb = smem_u32(smem);

    const int t   = threadIdx.x;
    const int l   = t & 31;
    const int wid = t >> 5;
    const int wm  = wid >> 2;
    const int wn  = wid & 3;
    const int row0 = blockIdx.y * 128, col0 = blockIdx.x * 128;

    const int KCH = Kdim >> 5;

    const int r1 = t >> 2, cc = t & 3;
    const int r2 = 64 + r1;
    const uint32_t so1 = (uint32_t)(r1 * 80 + cc * 16);
    const uint32_t so2 = (uint32_t)(r2 * 80 + cc * 16);

    float acc[4][4][4];
#pragma unroll
    for (int i = 0; i < 4; i++)
#pragma unroll
        for (int j = 0; j < 4; j++)
#pragma unroll
            for (int k = 0; k < 4; k++) acc[i][j][k] = 0.0f;

    auto issue = [&](int c) {
        const int k0 = c << 5;
        const uint32_t base = sb + (uint32_t)(c & 1) * GSTG;
        const __nv_bfloat16* a1 = Ahi + (size_t)(row0 + r1) * Kdim + k0 + cc * 8;
        const __nv_bfloat16* a2 = Ahi + (size_t)(row0 + r2) * Kdim + k0 + cc * 8;
        const __nv_bfloat16* b1 = Bhi + (size_t)(col0 + r1) * Kdim + k0 + cc * 8;
        const __nv_bfloat16* b2 = Bhi + (size_t)(col0 + r2) * Kdim + k0 + cc * 8;
        const size_t dA = (size_t)(Alo - Ahi);
        const size_t dB = (size_t)(Blo - Bhi);
        cpa16(base + so1,             a1);
        cpa16(base + so2,             a2);
        cpa16(base + GTILE + so1,     a1 + dA);
        cpa16(base + GTILE + so2,     a2 + dA);
        cpa16(base + 2 * GTILE + so1, b1);
        cpa16(base + 2 * GTILE + so2, b2);
        cpa16(base + 3 * GTILE + so1, b1 + dB);
        cpa16(base + 3 * GTILE + so2, b2 + dB);
        CPA_COMMIT();
    };

    issue(0);

    const uint32_t a_lrow = (uint32_t)(wm * 64 + (l & 15));
    const uint32_t a_lk   = (uint32_t)((l >> 4) * 8);
    const uint32_t b_lrow = (uint32_t)(wn * 32 + ((l >> 4) & 1) * 8 + (l & 7));
    const uint32_t b_lk   = (uint32_t)(((l >> 3) & 1) * 8);

    for (int c = 0; c < KCH; c++) {
        if (c + 1 < KCH) { issue(c + 1); CPA_WAIT(1); }
        else             { CPA_WAIT(0); }
        __syncthreads();

        const uint32_t stg = sb + (uint32_t)(c & 1) * GSTG;
        const uint32_t Ah = stg, Al = stg + GTILE;
        const uint32_t Bh = stg + 2 * GTILE, Bl = stg + 3 * GTILE;
#pragma unroll
        for (int ks = 0; ks < 2; ks++) {
            const uint32_t bko = (b_lk + (uint32_t)(ks * 16)) * 2u;
            uint32_t bfh[2][4], bfl[2][4];
#pragma unroll
            for (int np = 0; np < 2; np++) {
                const uint32_t ro = (b_lrow + (uint32_t)(np * 16)) * 80u + bko;
                LDSM_X4(bfh[np][0], bfh[np][1], bfh[np][2], bfh[np][3], Bh + ro);
                LDSM_X4(bfl[np][0], bfl[np][1], bfl[np][2], bfl[np][3], Bl + ro);
            }
            const uint32_t ako = (a_lk + (uint32_t)(ks * 16)) * 2u;
#pragma unroll
            for (int mt = 0; mt < 4; mt++) {
                const uint32_t aro = (a_lrow + (uint32_t)(mt * 16)) * 80u + ako;
                uint32_t af[4];
                LDSM_X4(af[0], af[1], af[2], af[3], Ah + aro);
#pragma unroll
                for (int nt = 0; nt < 4; nt++) {
                    const uint32_t* bp = &bfh[nt >> 1][(nt & 1) * 2];
                    MMA16816(acc[mt][nt], af, bp[0], bp[1]);
                }
#pragma unroll
                for (int nt = 0; nt < 4; nt++) {
                    const uint32_t* bp = &bfl[nt >> 1][(nt & 1) * 2];
                    MMA16816(acc[mt][nt], af, bp[0], bp[1]);
                }
                LDSM_X4(af[0], af[1], af[2], af[3], Al + aro);
#pragma unroll
                for (int nt = 0; nt < 4; nt++) {
                    const uint32_t* bp = &bfh[nt >> 1][(nt & 1) * 2];
                    MMA16816(acc[mt][nt], af, bp[0], bp[1]);
                }
            }
        }
        __syncthreads();
    }

    // Epilogue
    const int erow = row0 + wm * 64 + (l >> 2);
    const int ecol = col0 + wn * 32 + 2 * (l & 3);
    if (Cf) {
#pragma unroll
        for (int mt = 0; mt < 4; mt++)
#pragma unroll
            for (int nt = 0; nt < 4; nt++) {
                float2 v0 = {acc[mt][nt][0], acc[mt][nt][1]};
                float2 v1 = {acc[mt][nt][2], acc[mt][nt][3]};
                *(float2*)(Cf + (size_t)(erow + mt * 16)     * Ndim + ecol + nt * 8) = v0;
                *(float2*)(Cf + (size_t)(erow + mt * 16 + 8) * Ndim + ecol + nt * 8) = v1;
            }
    } else {
#pragma unroll
        for (int mt = 0; mt < 4; mt++)
#pragma unroll
            for (int nt = 0; nt < 4; nt++) {
                size_t o0 = (size_t)(erow + mt * 16)     * Ndim + ecol + nt * 8;
                size_t o1 = (size_t)(erow + mt * 16 + 8) * Ndim + ecol + nt * 8;
                *(uint32_t*)(Ch + o0) = pack_hi2(acc[mt][nt][0], acc[mt][nt][1]);
                *(uint32_t*)(Cl + o0) = pack_lo2(acc[mt][nt][0], acc[mt][nt][1]);
                *(uint32_t*)(Ch + o1) = pack_hi2(acc[mt][nt][2], acc[mt][nt][3]);
                *(uint32_t*)(Cl + o1) = pack_lo2(acc[mt][nt][2], acc[mt][nt][3]);
            }
    }
}

// ---------------------------------------------------------------------------
// fp32 -> (hi, lo) bf16 split (for x input)
// ---------------------------------------------------------------------------
__global__ __launch_bounds__(256) void split_kernel(
    const float* __restrict__ in, __nv_bfloat16* __restrict__ hi,
    __nv_bfloat16* __restrict__ lo, int n4)
{
    int i = blockIdx.x * blockDim.x + threadIdx.x;
    if (i >= n4) return;
    float4 v = ((const float4*)in)[i];
    uint2 ph = {pack_hi2(v.x, v.y), pack_hi2(v.z, v.w)};
    uint2 pl = {pack_lo2(v.x, v.y), pack_lo2(v.z, v.w)};
    ((uint2*)hi)[i] = ph;
    ((uint2*)lo)[i] = pl;
}

// ---------------------------------------------------------------------------
// fp32 [R][C] -> transposed bf16 hi/lo [C][R]
// ---------------------------------------------------------------------------
__global__ void tsplit_kernel(const float* __restrict__ in,
                              __nv_bfloat16* __restrict__ hiT,
                              __nv_bfloat16* __restrict__ loT, int R, int Cc)
{
    __shared__ float sm2[32][33];
    int c0 = blockIdx.x * 32, r0 = blockIdx.y * 32;
    int tx = threadIdx.x, ty = threadIdx.y;
#pragma unroll
    for (int i = ty; i < 32; i += 8)
        sm2[i][tx] = in[(size_t)(r0 + i) * Cc + c0 + tx];
    __syncthreads();
#pragma unroll
    for (int i = ty; i < 32; i += 8) {
        float v = sm2[tx][i];
        __nv_bfloat16 h = __float2bfloat16(v);
        __nv_bfloat16 lo = __float2bfloat16(v - __bfloat162float(h));
        size_t o = (size_t)(c0 + i) * R + r0 + tx;
        hiT[o] = h; loT[o] = lo;
    }
}

// ---------------------------------------------------------------------------
// Causal flash attention via mma.sync, pass-merged split-3, double-buffered
// K/V stages via cp.async.
// qkv hi/lo [row][3072]; out attn hi/lo [row][1024].
// Block 256 thr (8 warps); warp w: q-rows w*16..+15 of a 128-row tile.
// Smem: Qh/Ql 128x(72) + 2 stages x {Kh,Kl,Vh,Vl} 64x(72)  = 108 KB
// ---------------------------------------------------------------------------
#define APB 144
#define AQ_OFF  0
#define AQL_OFF (128 * APB)                 // 18432
#define ASTG0   (2 * 128 * APB)             // 36864
#define ASTGSZ  (4 * 64 * APB)              // 36864 per stage
#define ATTN_SMEM_BYTES (ASTG0 + 2 * ASTGSZ) // 110592

__global__ __launch_bounds__(256, 2)
void attn_mma_kernel(const __nv_bfloat16* __restrict__ qkvh,
                     const __nv_bfloat16* __restrict__ qkvl,
                     __nv_bfloat16* __restrict__ outh,
                     __nv_bfloat16* __restrict__ outl)
{
    extern __shared__ __align__(16) char smem[];
    const uint32_t sb = smem_u32(smem);

    const int t = threadIdx.x, l = t & 31, w = t >> 5;
    const int qt = blockIdx.x, h = blockIdx.y, b = blockIdx.z;
    const int q0 = qt * 128;

    // Q tile load (hi+lo), its own commit group
    {
#pragma unroll
        for (int i = 0; i < 4; i++) {
            int q = t + i * 256;
            int r = q >> 3, ch = q & 7;
            size_t g = (size_t)(b * S_ + q0 + r) * 3072 + h * HD_ + ch * 8;
            uint32_t s = (uint32_t)(r * APB + ch * 16);
            cpa16(sb + AQ_OFF + s,  qkvh + g);
            cpa16(sb + AQL_OFF + s, qkvl + g);
        }
        CPA_COMMIT();
    }

    const int r_ld = t >> 3, ch_ld = t & 7;
    const uint32_t s_ld = (uint32_t)(r_ld * APB + ch_ld * 16);
    const uint32_t s_ld2 = s_ld + 32 * APB;

    auto issue_kv = [&](int kt) {
        const int k0 = kt * 64;
        const uint32_t base = sb + ASTG0 + (uint32_t)(kt & 1) * ASTGSZ;
        size_t gk1 = (size_t)(b * S_ + k0 + r_ld) * 3072 + 1024 + h * HD_ + ch_ld * 8;
        size_t gk2 = gk1 + (size_t)32 * 3072;
        cpa16(base + s_ld,                   qkvh + gk1);
        cpa16(base + s_ld2,                  qkvh + gk2);
        cpa16(base + 9216 + s_ld,            qkvl + gk1);
        cpa16(base + 9216 + s_ld2,           qkvl + gk2);
        cpa16(base + 18432 + s_ld,           qkvh + gk1 + 1024);
        cpa16(base + 18432 + s_ld2,          qkvh + gk2 + 1024);
        cpa16(base + 27648 + s_ld,           qkvl + gk1 + 1024);
        cpa16(base + 27648 + s_ld2,          qkvl + gk2 + 1024);
        CPA_COMMIT();
    };

    issue_kv(0);

    float m0 = -INFINITY, m1 = -INFINITY, lr0 = 0.0f, lr1 = 0.0f;
    float O[8][4];
#pragma unroll
    for (int n = 0; n < 8; n++)
#pragma unroll
        for (int k = 0; k < 4; k++) O[n][k] = 0.0f;

    const uint32_t a_row = (uint32_t)(w * 16 + (l & 15));
    const uint32_t a_kd  = (uint32_t)((l >> 4) * 8);
    const uint32_t bk_j  = (uint32_t)(((l >> 4) & 1) * 8 + (l & 7));
    const uint32_t bk_d  = (uint32_t)(((l >> 3) & 1) * 8);
    const uint32_t bv_j  = (uint32_t)(((l >> 3) & 1) * 8 + (l & 7));
    const uint32_t bv_d  = (uint32_t)((l >> 4) * 8);

    const int ktiles = 2 * qt + 2;
    for (int kt = 0; kt < ktiles; kt++) {
        const int k0 = kt * 64;
        if (kt + 1 < ktiles) { issue_kv(kt + 1); CPA_WAIT(1); }
        else                 { CPA_WAIT(0); }
        __syncthreads();

        const uint32_t stg = sb + ASTG0 + (uint32_t)(kt & 1) * ASTGSZ;
        const uint32_t Kh = stg, Kl = stg + 9216;
        const uint32_t Vh = stg + 18432, Vl = stg + 27648;

        // ---- S = Q K^T, merged 3 products ----
        float S[8][4];
#pragma unroll
        for (int n = 0; n < 8; n++)
#pragma unroll
            for (int k = 0; k < 4; k++) S[n][k] = 0.0f;

#pragma unroll
        for (int ks = 0; ks < 4; ks++) {
            const uint32_t qro = a_row * APB + (a_kd + (uint32_t)(ks * 16)) * 2u;
            uint32_t aqh[4], aql[4];
            LDSM_X4(aqh[0], aqh[1], aqh[2], aqh[3], sb + AQ_OFF + qro);
            LDSM_X4(aql[0], aql[1], aql[2], aql[3], sb + AQL_OFF + qro);
            const uint32_t kdo = (bk_d + (uint32_t)(ks * 16)) * 2u;
#pragma unroll
            for (int jp = 0; jp < 4; jp++) {
                const uint32_t kro = (bk_j + (uint32_t)(jp * 16)) * APB + kdo;
                uint32_t bkh[4], bkl[4];
                LDSM_X4(bkh[0], bkh[1], bkh[2], bkh[3], Kh + kro);
                LDSM_X4(bkl[0], bkl[1], bkl[2], bkl[3], Kl + kro);
                MMA16816(S[2 * jp],     aqh, bkh[0], bkh[1]);
                MMA16816(S[2 * jp + 1], aqh, bkh[2], bkh[3]);
                MMA16816(S[2 * jp],     aqh, bkl[0], bkl[1]);
                MMA16816(S[2 * jp + 1], aqh, bkl[2], bkl[3]);
                MMA16816(S[2 * jp],     aql, bkh[0], bkh[1]);
                MMA16816(S[2 * jp + 1], aql, bkh[2], bkh[3]);
            }
        }

#pragma unroll
        for (int n = 0; n < 8; n++)
#pragma unroll
            for (int k = 0; k < 4; k++) S[n][k] *= 0.125f;

        if (kt >= 2 * qt) {
            const int gi0 = q0 + w * 16 + (l >> 2);
            const int gi1 = gi0 + 8;
#pragma unroll
            for (int n = 0; n < 8; n++) {
                const int gj = k0 + n * 8 + (l & 3) * 2;
                if (gj     > gi0) S[n][0] = -INFINITY;
                if (gj + 1 > gi0) S[n][1] = -INFINITY;
                if (gj     > gi1) S[n][2] = -INFINITY;
                if (gj + 1 > gi1) S[n][3] = -INFINITY;
            }
        }

        // ---- online softmax ----
        float mx0 = -INFINITY, mx1 = -INFINITY;
#pragma unroll
        for (int n = 0; n < 8; n++) {
            mx0 = fmaxf(mx0, fmaxf(S[n][0], S[n][1]));
            mx1 = fmaxf(mx1, fmaxf(S[n][2], S[n][3]));
        }
        mx0 = fmaxf(mx0, __shfl_xor_sync(0xffffffffu, mx0, 1));
        mx0 = fmaxf(mx0, __shfl_xor_sync(0xffffffffu, mx0, 2));
        mx1 = fmaxf(mx1, __shfl_xor_sync(0xffffffffu, mx1, 1));
        mx1 = fmaxf(mx1, __shfl_xor_sync(0xffffffffu, mx1, 2));
        const float mn0 = fmaxf(m0, mx0), mn1 = fmaxf(m1, mx1);
        const float corr0 = __expf(m0 - mn0), corr1 = __expf(m1 - mn1);
        m0 = mn0; m1 = mn1;
        float sum0 = 0.0f, sum1 = 0.0f;
#pragma unroll
        for (int n = 0; n < 8; n++) {
            S[n][0] = __expf(S[n][0] - mn0);
            S[n][1] = __expf(S[n][1] - mn0);
            S[n][2] = __expf(S[n][2] - mn1);
            S[n][3] = __expf(S[n][3] - mn1);
            sum0 += S[n][0] + S[n][1];
            sum1 += S[n][2] + S[n][3];
            O[n][0] *= corr0; O[n][1] *= corr0;
            O[n][2] *= corr1; O[n][3] *= corr1;
        }
        sum0 += __shfl_xor_sync(0xffffffffu, sum0, 1);
        sum0 += __shfl_xor_sync(0xffffffffu, sum0, 2);
        sum1 += __shfl_xor_sync(0xffffffffu, sum1, 1);
        sum1 += __shfl_xor_sync(0xffffffffu, sum1, 2);
        lr0 = lr0 * corr0 + sum0;
        lr1 = lr1 * corr1 + sum1;

        // ---- O += P V, merged 3 products ----
        uint32_t pfh[16], pfl[16];
#pragma unroll
        for (int ks = 0; ks < 4; ks++) {
            pfh[ks * 4 + 0] = pack_hi2(S[2 * ks][0],     S[2 * ks][1]);
            pfh[ks * 4 + 1] = pack_hi2(S[2 * ks][2],     S[2 * ks][3]);
            pfh[ks * 4 + 2] = pack_hi2(S[2 * ks + 1][0], S[2 * ks + 1][1]);
            pfh[ks * 4 + 3] = pack_hi2(S[2 * ks + 1][2], S[2 * ks + 1][3]);
            pfl[ks * 4 + 0] = pack_lo2(S[2 * ks][0],     S[2 * ks][1]);
            pfl[ks * 4 + 1] = pack_lo2(S[2 * ks][2],     S[2 * ks][3]);
            pfl[ks * 4 + 2] = pack_lo2(S[2 * ks + 1][0], S[2 * ks + 1][1]);
            pfl[ks * 4 + 3] = pack_lo2(S[2 * ks + 1][2], S[2 * ks + 1][3]);
        }
#pragma unroll
        for (int ks = 0; ks < 4; ks++) {
            const uint32_t vjo = (bv_j + (uint32_t)(ks * 16)) * APB;
#pragma unroll
            for (int np = 0; np < 4; np++) {
                const uint32_t vro = vjo + (bv_d + (uint32_t)(np * 16)) * 2u;
                uint32_t bvh[4], bvl[4];
                LDSM_X4T(bvh[0], bvh[1], bvh[2], bvh[3], Vh + vro);
                LDSM_X4T(bvl[0], bvl[1], bvl[2], bvl[3], Vl + vro);
                MMA16816(O[2 * np],     &pfh[ks * 4], bvh[0], bvh[1]);
                MMA16816(O[2 * np + 1], &pfh[ks * 4], bvh[2], bvh[3]);
                MMA16816(O[2 * np],     &pfh[ks * 4], bvl[0], bvl[1]);
                MMA16816(O[2 * np + 1], &pfh[ks * 4], bvl[2], bvl[3]);
                MMA16816(O[2 * np],     &pfl[ks * 4], bvh[0], bvh[1]);
                MMA16816(O[2 * np + 1], &pfl[ks * 4], bvh[2], bvh[3]);
            }
        }
        __syncthreads();
    }

    // ---- epilogue: normalize, write bf16 hi/lo ----
    const float inv0 = 1.0f / lr0, inv1 = 1.0f / lr1;
    const size_t row0g = (size_t)(b * S_ + q0 + w * 16 + (l >> 2));
    const size_t row1g = row0g + 8;
#pragma unroll
    for (int n = 0; n < 8; n++) {
        const int d0 = h * HD_ + n * 8 + (l & 3) * 2;
        float v0 = O[n][0] * inv0, v1 = O[n][1] * inv0;
        float v2 = O[n][2] * inv1, v3 = O[n][3] * inv1;
        *(uint32_t*)(outh + row0g * D_ + d0) = pack_hi2(v0, v1);
        *(uint32_t*)(outl + row0g * D_ + d0) = pack_lo2(v0, v1);
        *(uint32_t*)(outh + row1g * D_ + d0) = pack_hi2(v2, v3);
        *(uint32_t*)(outl + row1g * D_ + d0) = pack_lo2(v2, v3);
    }
}

// ---------------------------------------------------------------------------
extern "C" void kernel_launch(void* const* d_in, const int* in_sizes, int n_in,
                              void* d_out, int out_size)
{
    const float* x = nullptr; const float* wqkv = nullptr; const float* wout = nullptr;
    for (int i = 0; i < n_in; i++) {
        if (in_sizes[i] == 8388608)      x    = (const float*)d_in[i];
        else if (in_sizes[i] == 3145728) wqkv = (const float*)d_in[i];
        else if (in_sizes[i] == 1048576) wout = (const float*)d_in[i];
    }
    float* out = (float*)d_out;

    void* p;
    cudaGetSymbolAddress(&p, g_qkvh);     __nv_bfloat16* qkvh = (__nv_bfloat16*)p;
    cudaGetSymbolAddress(&p, g_qkvl);     __nv_bfloat16* qkvl = (__nv_bfloat16*)p;
    cudaGetSymbolAddress(&p, g_x_hi);     __nv_bfloat16* x_hi = (__nv_bfloat16*)p;
    cudaGetSymbolAddress(&p, g_x_lo);     __nv_bfloat16* x_lo = (__nv_bfloat16*)p;
    cudaGetSymbolAddress(&p, g_attn_hi);  __nv_bfloat16* a_hi = (__nv_bfloat16*)p;
    cudaGetSymbolAddress(&p, g_attn_lo);  __nv_bfloat16* a_lo = (__nv_bfloat16*)p;
    cudaGetSymbolAddress(&p, g_wqkvT_hi); __nv_bfloat16* wq_hi = (__nv_bfloat16*)p;
    cudaGetSymbolAddress(&p, g_wqkvT_lo); __nv_bfloat16* wq_lo = (__nv_bfloat16*)p;
    cudaGetSymbolAddress(&p, g_woutT_hi); __nv_bfloat16* wo_hi = (__nv_bfloat16*)p;
    cudaGetSymbolAddress(&p, g_woutT_lo); __nv_bfloat16* wo_lo = (__nv_bfloat16*)p;

    cudaFuncSetAttribute(gemm_mma_kernel, cudaFuncAttributeMaxDynamicSharedMemorySize,
                         GEMM_SMEM_BYTES);
    cudaFuncSetAttribute(attn_mma_kernel, cudaFuncAttributeMaxDynamicSharedMemorySize,
                         ATTN_SMEM_BYTES);

    // Weight split+transpose
    tsplit_kernel<<<dim3(3 * D_ / 32, D_ / 32), dim3(32, 8)>>>(wqkv, wq_hi, wq_lo, D_, 3 * D_);
    tsplit_kernel<<<dim3(D_ / 32, D_ / 32), dim3(32, 8)>>>(wout, wo_hi, wo_lo, D_, D_);
    // x split
    split_kernel<<<(M_ * D_ / 4 + 255) / 256, 256>>>(x, x_hi, x_lo, M_ * D_ / 4);

    // 1) qkv(hi/lo) = x @ W_qkv
    gemm_mma_kernel<<<dim3(3 * D_ / 128, M_ / 128), 256, GEMM_SMEM_BYTES>>>(
        x_hi, x_lo, wq_hi, wq_lo, nullptr, qkvh, qkvl, 3 * D_, D_);

    // 2) attention
    attn_mma_kernel<<<dim3(S_ / 128, H_, B_), 256, ATTN_SMEM_BYTES>>>(qkvh, qkvl, a_hi, a_lo);

    // 3) out = attn @ W_out  (fp32 out)
    gemm_mma_kernel<<<dim3(D_ / 128, M_ / 128), 256, GEMM_SMEM_BYTES>>>(
        a_hi, a_lo, wo_hi, wo_lo, out, nullptr, nullptr, D_, D_);
}